// round 2
// baseline (speedup 1.0000x reference)
#include <cuda_runtime.h>

#define N 192
#define NN (N * N)
#define NNN (N * N * N)
#define STEPS 20

// Ping buffer (pong is d_out). Scratch via __device__ global per harness rules.
__device__ float g_scratch[NNN];

__global__ __launch_bounds__(192) void rd_step_kernel(
    const float* __restrict__ src,
    float* __restrict__ dst,
    const float* __restrict__ Dm,
    const float* __restrict__ Rm,
    const float* __restrict__ dt_ptr)
{
    const int x = threadIdx.x;          // 0..191, contiguous dim
    const int y = blockIdx.y;           // 0..191
    const int z = blockIdx.z;           // 0..191
    const int idx = (z * N + y) * N + x;

    const float c = src[idx];

    // Zero-padded 7-point Laplacian: missing neighbors contribute 0,
    // center always contributes -6c (matches the reference padding semantics).
    float lap = -6.0f * c;
    if (x > 0)      lap += src[idx - 1];
    if (x < N - 1)  lap += src[idx + 1];
    if (y > 0)      lap += src[idx - N];
    if (y < N - 1)  lap += src[idx + N];
    if (z > 0)      lap += src[idx - NN];
    if (z < N - 1)  lap += src[idx + NN];

    const float delta_t = dt_ptr[0] * (1.0f / (float)STEPS);

    const float diffusion = Dm[idx] * lap;
    const float reaction  = Rm[idx] * c * (1.0f - c);
    float out = fmaf(diffusion + reaction, delta_t, c);

    // clip(0, 1)
    out = fminf(fmaxf(out, 0.0f), 1.0f);
    dst[idx] = out;
}

extern "C" void kernel_launch(void* const* d_in, const int* in_sizes, int n_in,
                              void* d_out, int out_size)
{
    const float* c_init = (const float*)d_in[0];
    const float* D_map  = (const float*)d_in[1];
    const float* rho    = (const float*)d_in[2];
    const float* dt     = (const float*)d_in[3];
    float* out = (float*)d_out;

    float* scratch = nullptr;
    cudaGetSymbolAddress((void**)&scratch, g_scratch);

    dim3 block(N, 1, 1);
    dim3 grid(1, N, N);

    // 20 steps, ping-pong. Step i writes to scratch when i is even, d_out when
    // i is odd; step 19 (last) lands in d_out.
    const float* src = c_init;
    for (int i = 0; i < STEPS; ++i) {
        float* dst = (i & 1) ? out : scratch;
        rd_step_kernel<<<grid, block>>>(src, dst, D_map, rho, dt);
        src = dst;
    }
}

// round 3
// speedup vs baseline: 3.2332x; 3.2332x over previous
#include <cuda_runtime.h>

#define N 192
#define NV (N / 4)          // 48 float4 per x-row
#define ROWS (N * N)        // 36864 rows
#define NNN (N * N * N)
#define STEPS 20

// Ping buffer (pong is d_out). float4 type forces 16B alignment.
__device__ float4 g_scratch4[NNN / 4];

__global__ __launch_bounds__(192) void rd_step_kernel(
    const float4* __restrict__ src4,
    float4* __restrict__ dst4,
    const float4* __restrict__ D4,
    const float4* __restrict__ R4,
    const float* __restrict__ dt_ptr)
{
    const int tx = threadIdx.x;                 // 0..47  (float4 column)
    const int y  = blockIdx.y * blockDim.y + threadIdx.y;  // 0..191
    const int z  = blockIdx.z;                  // 0..191
    const int row  = z * N + y;
    const int idx4 = row * NV + tx;

    const float* src = (const float*)src4;
    const int base = idx4 * 4;

    const float4 zero = make_float4(0.f, 0.f, 0.f, 0.f);

    // Wide loads — issued up-front for MLP.
    const float4 c  = src4[idx4];
    const float4 ym = (y > 0)     ? src4[idx4 - NV]     : zero;
    const float4 yp = (y < N - 1) ? src4[idx4 + NV]     : zero;
    const float4 zm = (z > 0)     ? src4[idx4 - NV * N] : zero;
    const float4 zp = (z < N - 1) ? src4[idx4 + NV * N] : zero;
    const float4 Dv = D4[idx4];
    const float4 Rv = R4[idx4];
    const float left  = (tx > 0)      ? src[base - 1] : 0.f;
    const float right = (tx < NV - 1) ? src[base + 4] : 0.f;

    const float delta_t = dt_ptr[0] * (1.0f / (float)STEPS);

    // Zero-padded 7-point Laplacian, x-neighbors mostly in-register.
    float4 lap;
    lap.x = left + c.y + ym.x + yp.x + zm.x + zp.x - 6.0f * c.x;
    lap.y = c.x  + c.z + ym.y + yp.y + zm.y + zp.y - 6.0f * c.y;
    lap.z = c.y  + c.w + ym.z + yp.z + zm.z + zp.z - 6.0f * c.z;
    lap.w = c.z  + right + ym.w + yp.w + zm.w + zp.w - 6.0f * c.w;

    float4 o;
    o.x = fmaf(fmaf(Dv.x, lap.x, Rv.x * c.x * (1.0f - c.x)), delta_t, c.x);
    o.y = fmaf(fmaf(Dv.y, lap.y, Rv.y * c.y * (1.0f - c.y)), delta_t, c.y);
    o.z = fmaf(fmaf(Dv.z, lap.z, Rv.z * c.z * (1.0f - c.z)), delta_t, c.z);
    o.w = fmaf(fmaf(Dv.w, lap.w, Rv.w * c.w * (1.0f - c.w)), delta_t, c.w);

    o.x = fminf(fmaxf(o.x, 0.f), 1.f);
    o.y = fminf(fmaxf(o.y, 0.f), 1.f);
    o.z = fminf(fmaxf(o.z, 0.f), 1.f);
    o.w = fminf(fmaxf(o.w, 0.f), 1.f);

    dst4[idx4] = o;
}

extern "C" void kernel_launch(void* const* d_in, const int* in_sizes, int n_in,
                              void* d_out, int out_size)
{
    const float4* c_init = (const float4*)d_in[0];
    const float4* D_map  = (const float4*)d_in[1];
    const float4* rho    = (const float4*)d_in[2];
    const float*  dt     = (const float*)d_in[3];
    float4* out = (float4*)d_out;

    float4* scratch = nullptr;
    cudaGetSymbolAddress((void**)&scratch, g_scratch4);

    dim3 block(NV, 4, 1);       // 48 x 4 = 192 threads
    dim3 grid(1, N / 4, N);     // (1, 48, 192)

    const float4* src = c_init;
    for (int i = 0; i < STEPS; ++i) {
        float4* dst = (i & 1) ? out : scratch;
        rd_step_kernel<<<grid, block>>>(src, dst, D_map, rho, dt);
        src = dst;
    }
}